// round 5
// baseline (speedup 1.0000x reference)
#include <cuda_runtime.h>
#include <cstdint>
#include <cstddef>

// SNN Leaky scan. reset_t = H(mem_{t-1}-1); mem_t = beta*mem_{t-1}+x_t-reset_t; spk_t = H(mem_t-1)
// Exact numerics: mem = fma(beta,mem,x) - r (a-r is exact by Sterbenz; matches reference, rel_err=0).
//
// KEY CHANGE vs R4: each compute thread runs TWO independent rows interleaved
// (rows k and k+32), so the 8-cyc dependency chain of one row is filled by the
// other row's instructions + LDS/STS. 1 compute warp + 2 io warps per CTA.
// 25 chunks of 160 steps (no tail). Odd row stride (41 float4) => conflict-free
// LDS/STS.128 with no XOR swizzle.

namespace {
constexpr int N_TOTAL  = 8192;
constexpr int T_STEPS  = 4000;
constexpr float BETA   = 0.95f;

constexpr int ROWS     = 64;      // rows per CTA
constexpr int CTHREADS = 32;      // compute warp (2 rows per thread)
constexpr int THREADS  = 96;      // + 2 io warps
constexpr int TCHUNK   = 160;     // 25 * 160 = 4000 exactly
constexpr int TC4      = TCHUNK / 4;     // 40 float4 per row-chunk
constexpr int NCHUNK   = T_STEPS / TCHUNK;   // 25
constexpr int RSTRIDE  = TC4 + 1;            // 41: odd f4 stride -> conflict-free
constexpr int BUFELEM  = ROWS * RSTRIDE;     // float4 per buffer
constexpr size_t SMEM_BYTES = (size_t)(3 + 2) * BUFELEM * sizeof(float4);  // 205 KB
}

__device__ __forceinline__ void cp_async16(void* sdst, const void* gsrc) {
    uint32_t s = (uint32_t)__cvta_generic_to_shared(sdst);
    asm volatile("cp.async.cg.shared.global [%0], [%1], 16;" :: "r"(s), "l"(gsrc));
}
__device__ __forceinline__ void cp_commit() {
    asm volatile("cp.async.commit_group;" ::: "memory");
}
template <int NN>
__device__ __forceinline__ void cp_wait() {
    asm volatile("cp.async.wait_group %0;" :: "n"(NN) : "memory");
}

__device__ __forceinline__ float fset_gt1(float v) {
    float r;
    asm("set.gt.f32.f32 %0, %1, %2;" : "=f"(r) : "f"(v), "f"(1.0f));
    return r;
}

// On entry r == reset_t (= spk_{t-1}); on exit r == spk_t.
__device__ __forceinline__ void snn_step(float& mem, float& r, float x, float& spk) {
    float a = __fmaf_rn(BETA, mem, x);
    mem = a - r;              // exact (Sterbenz); FFMA(4)->FADD(4) chain
    r = fset_gt1(mem);
    spk = r;
}

__global__ void __launch_bounds__(THREADS, 1)
snn_leaky_ws_kernel(const float* __restrict__ inp, float* __restrict__ out) {
    extern __shared__ float4 smem[];
    const int tid  = threadIdx.x;
    const int lane = tid & 31;
    const int rowBase = blockIdx.x * ROWS;
    const bool is_io = (tid >= CTHREADS);
    const int iow = (tid - CTHREADS) >> 5;   // 0 or 1 (io warps only)

    float4* inbuf[3]  = { smem, smem + BUFELEM, smem + 2 * BUFELEM };
    float4* outbuf[2] = { smem + 3 * BUFELEM, smem + 4 * BUFELEM };

    // ---- prologue: io warps preload chunks 0 and 1 (one commit group each) ----
    if (is_io) {
        for (int c0 = 0; c0 < 2; ++c0) {
            for (int r = iow; r < ROWS; r += 2) {
                const float4* g = reinterpret_cast<const float4*>(
                    inp + (size_t)(rowBase + r) * T_STEPS + c0 * TCHUNK);
                float4* d = &inbuf[c0][r * RSTRIDE];
                #pragma unroll
                for (int i = lane; i < TC4; i += 32) cp_async16(d + i, g + i);
            }
            cp_commit();
        }
    }

    // two independent chains per compute thread: rows (tid) and (tid+32)
    float memA = 0.0f, rA = 0.0f;
    float memB = 0.0f, rB = 0.0f;

    for (int c = 0; c <= NCHUNK; ++c) {
        if (is_io) cp_wait<1>();   // input chunk c landed (<=1 group outstanding)
        __syncthreads();

        if (!is_io) {
            if (c < NCHUNK) {
                const float4* __restrict__ rinA  = inbuf[c % 3] + tid * RSTRIDE;
                const float4* __restrict__ rinB  = rinA + 32 * RSTRIDE;
                float4* __restrict__       routA = outbuf[c & 1] + tid * RSTRIDE;
                float4* __restrict__       routB = routA + 32 * RSTRIDE;
                #pragma unroll
                for (int t4 = 0; t4 < TC4; ++t4) {
                    float4 xA = rinA[t4];          // conflict-free LDS.128 (odd stride)
                    float4 xB = rinB[t4];
                    float4 sA, sB;
                    // interleave the two chains so each fills the other's stalls
                    snn_step(memA, rA, xA.x, sA.x);  snn_step(memB, rB, xB.x, sB.x);
                    snn_step(memA, rA, xA.y, sA.y);  snn_step(memB, rB, xB.y, sB.y);
                    snn_step(memA, rA, xA.z, sA.z);  snn_step(memB, rB, xB.z, sB.z);
                    snn_step(memA, rA, xA.w, sA.w);  snn_step(memB, rB, xB.w, sB.w);
                    routA[t4] = sA;                // conflict-free STS.128
                    routB[t4] = sB;
                }
            }
        } else {
            // ---- store spikes of chunk c-1 (coalesced float4 STG) ----
            if (c >= 1) {
                const int cp = c - 1;
                const float4* b = outbuf[cp & 1];
                for (int r = iow; r < ROWS; r += 2) {
                    float4* g = reinterpret_cast<float4*>(
                        out + (size_t)(rowBase + r) * T_STEPS + cp * TCHUNK);
                    const float4* s = &b[r * RSTRIDE];
                    #pragma unroll
                    for (int i = lane; i < TC4; i += 32) g[i] = s[i];
                }
            }
            // ---- prefetch input chunk c+2 ----
            if (c + 2 < NCHUNK) {
                const int cn = c + 2;
                float4* b = inbuf[cn % 3];
                for (int r = iow; r < ROWS; r += 2) {
                    const float4* g = reinterpret_cast<const float4*>(
                        inp + (size_t)(rowBase + r) * T_STEPS + cn * TCHUNK);
                    float4* d = &b[r * RSTRIDE];
                    #pragma unroll
                    for (int i = lane; i < TC4; i += 32) cp_async16(d + i, g + i);
                }
            }
            cp_commit();   // unconditional: uniform group counting
        }
    }
}

extern "C" void kernel_launch(void* const* d_in, const int* in_sizes, int n_in,
                              void* d_out, int out_size) {
    (void)in_sizes; (void)n_in; (void)out_size;
    const float* inp = (const float*)d_in[0];
    float* out = (float*)d_out;

    cudaFuncSetAttribute(snn_leaky_ws_kernel,
                         cudaFuncAttributeMaxDynamicSharedMemorySize,
                         (int)SMEM_BYTES);
    snn_leaky_ws_kernel<<<N_TOTAL / ROWS, THREADS, SMEM_BYTES>>>(inp, out);
}

// round 6
// speedup vs baseline: 1.1188x; 1.1188x over previous
#include <cuda_runtime.h>
#include <cstdint>
#include <cstddef>

// SNN Leaky scan. reset_t = H(mem_{t-1}-1); mem_t = beta*mem_{t-1}+x_t-reset_t; spk_t = H(mem_t-1)
//
// KEY CHANGE vs all prior rounds: the Heaviside is computed WITHOUT any
// comparison (FSETP lat=13 was sitting on the loop-carried cycle and pinned
// every previous version at ~21 cyc/step). Instead:
//     r = fma.rn.sat.f32(mem, 2^25, -2^25)
// Exact: (mem-1)*2^25 computed single-rounded; mem>1 => >=2 -> sat 1;
// mem<=1 => <=0 -> sat 0 (sign preserved by single rounding). Bit-exact vs
// the reference's (mem > 1) ? 1 : 0 for the reachable range mem in (-1, 2).
// All ops in the carried cycle are now fixed-lat-4 fma-pipe: period = 8 cyc/step.
//
// Warps 0-1: compute (thread t owns row t). Warps 2-3: all global I/O.
// Input ring: 3 buffers (cp.async, 2 chunks ahead). Output: 2 ping-pong buffers.
// XOR-swizzled tiles: conflict-free LDS/STS.128. One __syncthreads per chunk.

namespace {
constexpr int N_TOTAL  = 8192;
constexpr int T_STEPS  = 4000;
constexpr float BETA   = 0.95f;

constexpr int ROWS     = 64;     // rows per CTA
constexpr int CTHREADS = 64;     // compute threads (warps 0,1)
constexpr int THREADS  = 128;    // + io warps 2,3
constexpr int TCHUNK   = 128;    // time steps per chunk
constexpr int TC4      = TCHUNK / 4;                          // 32 float4 per row-chunk
constexpr int NCHUNK   = (T_STEPS + TCHUNK - 1) / TCHUNK;     // 32 (31 full + 32-step tail)
constexpr int TAIL4    = (T_STEPS - (NCHUNK - 1) * TCHUNK) / 4;  // 8
constexpr int BUFELEM  = ROWS * TC4;                          // float4 per buffer
constexpr size_t SMEM_BYTES = (size_t)(3 + 2) * BUFELEM * sizeof(float4);  // 160 KB
}

__device__ __forceinline__ void cp_async16(void* sdst, const void* gsrc) {
    uint32_t s = (uint32_t)__cvta_generic_to_shared(sdst);
    asm volatile("cp.async.cg.shared.global [%0], [%1], 16;" :: "r"(s), "l"(gsrc));
}
__device__ __forceinline__ void cp_commit() {
    asm volatile("cp.async.commit_group;" ::: "memory");
}
template <int NN>
__device__ __forceinline__ void cp_wait() {
    asm volatile("cp.async.wait_group %0;" :: "n"(NN) : "memory");
}

// Heaviside H(v - 1) as a single saturating FFMA (lat 4, fma pipe, no predicate).
__device__ __forceinline__ float heaviside_gt1(float v) {
    const float BIG = 33554432.0f;   // 2^25
    float r;
    asm("fma.rn.sat.f32 %0, %1, %2, %3;" : "=f"(r) : "f"(v), "f"(BIG), "f"(-BIG));
    return r;
}

// On entry r == reset_t (= spk_{t-1}); on exit r == spk_t.
// Carried cycle: FFMA(4) -> FADD(4) on mem; FFMA.SAT(4) feeds next FADD. P = 8.
__device__ __forceinline__ void snn_step(float& mem, float& r, float x, float& spk) {
    float a = __fmaf_rn(BETA, mem, x);
    mem = a - r;              // exact: r in {0,1}, same arithmetic as reference
    r = heaviside_gt1(mem);
    spk = r;
}

__device__ __forceinline__ float4 snn_step4(float& mem, float& r, float4 x) {
    float4 s;
    snn_step(mem, r, x.x, s.x);
    snn_step(mem, r, x.y, s.y);
    snn_step(mem, r, x.z, s.z);
    snn_step(mem, r, x.w, s.w);
    return s;
}

__global__ void __launch_bounds__(THREADS, 1)
snn_leaky_ws_kernel(const float* __restrict__ inp, float* __restrict__ out) {
    extern __shared__ float4 smem[];
    const int tid  = threadIdx.x;
    const int lane = tid & 31;
    const int rowBase = blockIdx.x * ROWS;
    const bool is_io = (tid >= CTHREADS);
    const int iow = (tid - CTHREADS) >> 5;   // 0 or 1 (io warps only)

    float4* inbuf[3]  = { smem, smem + BUFELEM, smem + 2 * BUFELEM };
    float4* outbuf[2] = { smem + 3 * BUFELEM, smem + 4 * BUFELEM };

    // ---- prologue: io warps preload chunks 0 and 1 (one commit group each) ----
    if (is_io) {
        for (int c0 = 0; c0 < 2; ++c0) {
            for (int r = iow; r < ROWS; r += 2) {
                const float4* g = reinterpret_cast<const float4*>(
                    inp + (size_t)(rowBase + r) * T_STEPS + c0 * TCHUNK);
                cp_async16(&inbuf[c0][r * TC4 + (lane ^ (r & 31))], g + lane);
            }
            cp_commit();
        }
    }

    float mem = 0.0f, rst = 0.0f;

    for (int c = 0; c <= NCHUNK; ++c) {
        if (is_io) cp_wait<1>();   // input chunk c landed (<=1 group outstanding)
        __syncthreads();

        if (!is_io) {
            if (c < NCHUNK) {
                const float4* __restrict__ rin  = inbuf[c % 3] + tid * TC4;
                float4* __restrict__       rout = outbuf[c & 1] + tid * TC4;
                const int sw = tid & 31;
                if (c != NCHUNK - 1) {
                    float4 xa = rin[0 ^ sw];          // LDS pipelined 2 iters ahead
                    float4 xb = rin[1 ^ sw];
                    #pragma unroll
                    for (int t4 = 0; t4 < TC4; ++t4) {
                        float4 xc;
                        if (t4 + 2 < TC4) xc = rin[(t4 + 2) ^ sw];
                        rout[t4 ^ sw] = snn_step4(mem, rst, xa);
                        xa = xb; xb = xc;
                    }
                } else {
                    float4 xa = rin[0 ^ sw];
                    float4 xb = rin[1 ^ sw];
                    #pragma unroll
                    for (int t4 = 0; t4 < TAIL4; ++t4) {
                        float4 xc;
                        if (t4 + 2 < TAIL4) xc = rin[(t4 + 2) ^ sw];
                        rout[t4 ^ sw] = snn_step4(mem, rst, xa);
                        xa = xb; xb = xc;
                    }
                }
            }
        } else {
            // ---- store spikes of chunk c-1 (coalesced float4 STG) ----
            if (c >= 1) {
                const int cp = c - 1;
                const int nv4 = (cp == NCHUNK - 1) ? TAIL4 : TC4;
                const float4* b = outbuf[cp & 1];
                for (int r = iow; r < ROWS; r += 2) {
                    if (lane < nv4) {
                        float4 v = b[r * TC4 + (lane ^ (r & 31))];
                        reinterpret_cast<float4*>(
                            out + (size_t)(rowBase + r) * T_STEPS + cp * TCHUNK)[lane] = v;
                    }
                }
            }
            // ---- prefetch input chunk c+2 ----
            if (c + 2 < NCHUNK) {
                const int cn = c + 2;
                const int nv4 = (cn == NCHUNK - 1) ? TAIL4 : TC4;
                float4* b = inbuf[cn % 3];
                for (int r = iow; r < ROWS; r += 2) {
                    if (lane < nv4) {
                        const float4* g = reinterpret_cast<const float4*>(
                            inp + (size_t)(rowBase + r) * T_STEPS + cn * TCHUNK);
                        cp_async16(&b[r * TC4 + (lane ^ (r & 31))], g + lane);
                    }
                }
            }
            cp_commit();   // unconditional: uniform group counting
        }
    }
}

extern "C" void kernel_launch(void* const* d_in, const int* in_sizes, int n_in,
                              void* d_out, int out_size) {
    (void)in_sizes; (void)n_in; (void)out_size;
    const float* inp = (const float*)d_in[0];
    float* out = (float*)d_out;

    cudaFuncSetAttribute(snn_leaky_ws_kernel,
                         cudaFuncAttributeMaxDynamicSharedMemorySize,
                         (int)SMEM_BYTES);
    snn_leaky_ws_kernel<<<N_TOTAL / ROWS, THREADS, SMEM_BYTES>>>(inp, out);
}

// round 7
// speedup vs baseline: 1.2488x; 1.1162x over previous
#include <cuda_runtime.h>
#include <cstdint>
#include <cstddef>

// SNN Leaky scan. reset_t = H(mem_{t-1}-1); mem_t = beta*mem_{t-1}+x_t-reset_t; spk_t = H(mem_t-1)
// Heaviside via saturating FFMA (no predicate): r = fma.rn.sat(mem, 2^25, -2^25).
// Exact vs reference (strict >): mem>1 => (mem-1)*2^25 >= 4 -> sat 1; mem<=1 => <=0 -> sat 0.
//
// KEY CHANGE vs R6: 256 CTAs x 32 rows (was 128 x 64). Each CTA = 1 compute warp
// + 1 io warp, 84KB smem -> 2 CTAs co-resident per SM. Two independent pipelines
// per SM overlap each other's latency (chain bubbles, LDS, STG issue, barriers),
// which intra-warp scheduling provably could not fix (R2-R6 all identical).

namespace {
constexpr int N_TOTAL  = 8192;
constexpr int T_STEPS  = 4000;
constexpr float BETA   = 0.95f;

constexpr int ROWS     = 32;     // rows per CTA (1 per compute thread)
constexpr int CTHREADS = 32;     // compute warp
constexpr int THREADS  = 64;     // + 1 io warp
constexpr int TCHUNK   = 128;    // time steps per chunk
constexpr int TC4      = TCHUNK / 4;                          // 32 float4 per row-chunk
constexpr int NCHUNK   = (T_STEPS + TCHUNK - 1) / TCHUNK;     // 32 (31 full + 32-step tail)
constexpr int TAIL4    = (T_STEPS - (NCHUNK - 1) * TCHUNK) / 4;  // 8
constexpr int RSTRIDE  = TC4 + 1;                             // 33: odd stride, conflict-free
constexpr int BUFELEM  = ROWS * RSTRIDE;                      // float4 per buffer
constexpr size_t SMEM_BYTES = (size_t)(3 + 2) * BUFELEM * sizeof(float4);  // 84.5 KB
}

__device__ __forceinline__ void cp_async16(void* sdst, const void* gsrc) {
    uint32_t s = (uint32_t)__cvta_generic_to_shared(sdst);
    asm volatile("cp.async.cg.shared.global [%0], [%1], 16;" :: "r"(s), "l"(gsrc));
}
__device__ __forceinline__ void cp_commit() {
    asm volatile("cp.async.commit_group;" ::: "memory");
}
template <int NN>
__device__ __forceinline__ void cp_wait() {
    asm volatile("cp.async.wait_group %0;" :: "n"(NN) : "memory");
}

// Heaviside H(v - 1) as a single saturating FFMA (lat 4, fma pipe, no predicate).
__device__ __forceinline__ float heaviside_gt1(float v) {
    const float BIG = 33554432.0f;   // 2^25
    float r;
    asm("fma.rn.sat.f32 %0, %1, %2, %3;" : "=f"(r) : "f"(v), "f"(BIG), "f"(-BIG));
    return r;
}

// On entry r == reset_t (= spk_{t-1}); on exit r == spk_t. Carried cycle P = 8.
__device__ __forceinline__ void snn_step(float& mem, float& r, float x, float& spk) {
    float a = __fmaf_rn(BETA, mem, x);
    mem = a - r;              // exact: r in {0,1}
    r = heaviside_gt1(mem);
    spk = r;
}

__device__ __forceinline__ float4 snn_step4(float& mem, float& r, float4 x) {
    float4 s;
    snn_step(mem, r, x.x, s.x);
    snn_step(mem, r, x.y, s.y);
    snn_step(mem, r, x.z, s.z);
    snn_step(mem, r, x.w, s.w);
    return s;
}

__global__ void __launch_bounds__(THREADS, 2)
snn_leaky_ws_kernel(const float* __restrict__ inp, float* __restrict__ out) {
    extern __shared__ float4 smem[];
    const int tid  = threadIdx.x;
    const int lane = tid & 31;
    const int rowBase = blockIdx.x * ROWS;
    const bool is_io = (tid >= CTHREADS);

    float4* inbuf[3]  = { smem, smem + BUFELEM, smem + 2 * BUFELEM };
    float4* outbuf[2] = { smem + 3 * BUFELEM, smem + 4 * BUFELEM };

    // ---- prologue: io warp preloads chunks 0 and 1 (one commit group each) ----
    if (is_io) {
        for (int c0 = 0; c0 < 2; ++c0) {
            for (int r = 0; r < ROWS; ++r) {
                const float4* g = reinterpret_cast<const float4*>(
                    inp + (size_t)(rowBase + r) * T_STEPS + c0 * TCHUNK);
                cp_async16(&inbuf[c0][r * RSTRIDE + lane], g + lane);
            }
            cp_commit();
        }
    }

    float mem = 0.0f, rst = 0.0f;

    for (int c = 0; c <= NCHUNK; ++c) {
        if (is_io) cp_wait<1>();   // input chunk c landed (<=1 group outstanding)
        __syncthreads();

        if (!is_io) {
            if (c < NCHUNK) {
                const float4* __restrict__ rin  = inbuf[c % 3] + tid * RSTRIDE;
                float4* __restrict__       rout = outbuf[c & 1] + tid * RSTRIDE;
                if (c != NCHUNK - 1) {
                    float4 xa = rin[0];            // LDS pipelined 2 iters ahead
                    float4 xb = rin[1];
                    #pragma unroll
                    for (int t4 = 0; t4 < TC4; ++t4) {
                        float4 xc;
                        if (t4 + 2 < TC4) xc = rin[t4 + 2];
                        rout[t4] = snn_step4(mem, rst, xa);
                        xa = xb; xb = xc;
                    }
                } else {
                    float4 xa = rin[0];
                    float4 xb = rin[1];
                    #pragma unroll
                    for (int t4 = 0; t4 < TAIL4; ++t4) {
                        float4 xc;
                        if (t4 + 2 < TAIL4) xc = rin[t4 + 2];
                        rout[t4] = snn_step4(mem, rst, xa);
                        xa = xb; xb = xc;
                    }
                }
            }
        } else {
            // ---- store spikes of chunk c-1 (coalesced float4 STG) ----
            if (c >= 1) {
                const int cp = c - 1;
                const int nv4 = (cp == NCHUNK - 1) ? TAIL4 : TC4;
                const float4* b = outbuf[cp & 1];
                if (lane < nv4) {
                    #pragma unroll 4
                    for (int r = 0; r < ROWS; ++r) {
                        float4 v = b[r * RSTRIDE + lane];
                        reinterpret_cast<float4*>(
                            out + (size_t)(rowBase + r) * T_STEPS + cp * TCHUNK)[lane] = v;
                    }
                }
            }
            // ---- prefetch input chunk c+2 ----
            if (c + 2 < NCHUNK) {
                const int cn = c + 2;
                const int nv4 = (cn == NCHUNK - 1) ? TAIL4 : TC4;
                float4* b = inbuf[cn % 3];
                if (lane < nv4) {
                    #pragma unroll 4
                    for (int r = 0; r < ROWS; ++r) {
                        const float4* g = reinterpret_cast<const float4*>(
                            inp + (size_t)(rowBase + r) * T_STEPS + cn * TCHUNK);
                        cp_async16(&b[r * RSTRIDE + lane], g + lane);
                    }
                }
            }
            cp_commit();   // unconditional: uniform group counting
        }
    }
}

extern "C" void kernel_launch(void* const* d_in, const int* in_sizes, int n_in,
                              void* d_out, int out_size) {
    (void)in_sizes; (void)n_in; (void)out_size;
    const float* inp = (const float*)d_in[0];
    float* out = (float*)d_out;

    cudaFuncSetAttribute(snn_leaky_ws_kernel,
                         cudaFuncAttributeMaxDynamicSharedMemorySize,
                         (int)SMEM_BYTES);
    snn_leaky_ws_kernel<<<N_TOTAL / ROWS, THREADS, SMEM_BYTES>>>(inp, out);
}